// round 14
// baseline (speedup 1.0000x reference)
#include <cuda_runtime.h>
#include <cuda_fp16.h>
#include <cstdint>

#define N_NODES 100000
#define N_EDGES 1600000

// ---------------------------------------------------------------------------
// Device scratch
// ---------------------------------------------------------------------------
__device__ float4 g_msg[(size_t)N_NODES * 32];   // 51.2 MB
__device__ __half g_w[5 * 128 * 128];            // W^T fp16 planes [chunk][n][k]
__device__ int    g_mode;

// ---------------------------------------------------------------------------
// weight prep (transpose to [n][k], fp16) + edge_index dtype detection
// chunk 0,1 = W0 (k 0-127 / 128-255); 2,3 = Wh[0],Wh[1]; 4 = Wo
// ---------------------------------------------------------------------------
__global__ void prep_kernel(const float* __restrict__ W0,
                            const float* __restrict__ Wh,
                            const float* __restrict__ Wo,
                            const void* eiv) {
    if (blockIdx.x == 0 && threadIdx.x == 0) {
        const long long* e64 = (const long long*)eiv;
        const int*       e32 = (const int*)eiv;
        const float*     ef  = (const float*)eiv;
        bool ok64 = true, ok32 = true, okf = true;
        for (int i = 0; i < 32; i++) {
            long long v = e64[i];
            if (v < 0 || v >= N_NODES) ok64 = false;
            int w = e32[i];
            if (w < 0 || w >= N_NODES) ok32 = false;
            float f = ef[i];
            if (!(f >= 0.f && f < (float)N_NODES)) okf = false;
        }
        g_mode = ok64 ? 1 : (ok32 ? 0 : (okf ? 2 : 0));
    }
    int i = blockIdx.x * 256 + threadIdx.x;
    if (i >= 5 * 128 * 128) return;
    int chunk = i >> 14;
    int r = i & 16383;
    int n = r >> 7, k = r & 127;
    float v;
    if (chunk < 2)      v = W0[(chunk * 128 + k) * 128 + n];
    else if (chunk < 4) v = Wh[(chunk - 2) * 16384 + k * 128 + n];
    else                v = Wo[k * 128 + n];
    g_w[i] = __float2half_rn(v);
}

__global__ void zero_kernel(float4* __restrict__ p, int n4) {
    int i = blockIdx.x * blockDim.x + threadIdx.x;
    if (i < n4) p[i] = make_float4(0.f, 0.f, 0.f, 0.f);
}

// no-op: shifts scatter into ncu's captured launch slot (index 3)
__global__ void dummy_kernel() {}

// ---------------------------------------------------------------------------
// scatter-sum: one warp per edge, lane handles 16 B of the 512 B edge row,
// vector RED into the L2-resident msg buffer. (R8 config — best known.)
// ---------------------------------------------------------------------------
__global__ void scatter_kernel(const float4* __restrict__ e4,
                               const void* __restrict__ eiv,
                               float4* __restrict__ msg) {
    __shared__ int mode;
    if (threadIdx.x == 0) mode = g_mode;
    __syncthreads();
    int warp = (blockIdx.x * blockDim.x + threadIdx.x) >> 5;
    int lane = threadIdx.x & 31;
    if (warp >= N_EDGES) return;
    int d;
    if (mode == 1)      d = (int)((const long long*)eiv)[N_EDGES + warp];
    else if (mode == 0) d = ((const int*)eiv)[N_EDGES + warp];
    else                d = (int)((const float*)eiv)[N_EDGES + warp];
    d = min(max(d, 0), N_NODES - 1);
    float4 v = e4[(size_t)warp * 32 + lane];
    float4* p = &msg[(size_t)d * 32 + lane];
    asm volatile("red.global.add.v4.f32 [%0], {%1,%2,%3,%4};"
                 :: "l"(p), "f"(v.x), "f"(v.y), "f"(v.z), "f"(v.w) : "memory");
}

// ---------------------------------------------------------------------------
// Fused 4-layer MLP, persistent-CTA version: grid = #SMs, each CTA stages all
// 5 weight chunks ONCE, then loops over 128-row tiles. 512 threads, 16 warps
// in 4x4 grid (32x32 each). Explicit mma.sync.m16n8k16 + ldmatrix; bias/ReLU/
// fp16-convert in registers; A plane rewritten in place between layers.
// smem: A fp16 plane 128x272B | W chunks 5x(128x272B) = 208,960 B.
// ---------------------------------------------------------------------------
#define SSTR 136
#define SB   272                         // bytes per plane row
#define SA   0
#define SWB  (128 * SB)                  // 34816: W region base
#define WCH  (128 * SB)                  // per-chunk size
#define SMEM_T (SWB + 5 * WCH + 64)      // 208960

__device__ __forceinline__ void ldsm4(uint32_t& r0, uint32_t& r1,
                                      uint32_t& r2, uint32_t& r3, uint32_t a) {
    asm volatile("ldmatrix.sync.aligned.m8n8.x4.shared.b16 {%0,%1,%2,%3}, [%4];"
                 : "=r"(r0), "=r"(r1), "=r"(r2), "=r"(r3) : "r"(a));
}

__device__ __forceinline__ void mma16816(float* d, const uint32_t* a, const uint32_t* b) {
    asm volatile("mma.sync.aligned.m16n8k16.row.col.f32.f16.f16.f32 "
                 "{%0,%1,%2,%3}, {%4,%5,%6,%7}, {%8,%9}, {%0,%1,%2,%3};"
                 : "+f"(d[0]), "+f"(d[1]), "+f"(d[2]), "+f"(d[3])
                 : "r"(a[0]), "r"(a[1]), "r"(a[2]), "r"(a[3]), "r"(b[0]), "r"(b[1]));
}

__global__ void __launch_bounds__(512, 1)
fused_mlp_kernel(const float* __restrict__ x, const float* __restrict__ msgf,
                 const __half* __restrict__ W_g,
                 const float* __restrict__ b0, const float* __restrict__ bh,
                 const float* __restrict__ bo,
                 const float* __restrict__ gw, const float* __restrict__ gb,
                 float* __restrict__ outf, int nrows, int ntiles) {
    extern __shared__ char smem[];
    const int tid  = threadIdx.x;
    const int wid  = tid >> 5, lane = tid & 31;
    const int wy   = wid >> 2, wx = wid & 3;      // 4x4 warp grid, 32x32 tiles
    const int g    = lane >> 2, tig = lane & 3;   // mma quad coords

    // ---- stage ALL weight chunks once per CTA (10240 uint4) ----
    {
        const uint4* w4 = (const uint4*)W_g;
        #pragma unroll
        for (int it = 0; it < 20; it++) {
            int i = tid + it * 512;
            int chunk = i >> 11;
            int n = (i & 2047) >> 4, c16 = i & 15;
            *(uint4*)(smem + SWB + chunk * WCH + n * SB + c16 * 16) = w4[i];
        }
    }
    __syncthreads();

    // ldmatrix lane-address components
    const uint32_t sbase = (uint32_t)__cvta_generic_to_shared(smem);
    const uint32_t a_row = wy * 32 + (lane & 15);           // + i*16
    const uint32_t a_k   = (lane >> 4) << 3;
    const uint32_t b_row = wx * 32 + (lane & 7) + ((lane >> 4) << 3);  // + p*16
    const uint32_t b_k   = ((lane >> 3) & 1) << 3;
    const uint32_t a_base = sbase + SA + a_row * SB + a_k * 2;
    const uint32_t b_base0 = sbase + SWB + b_row * SB + b_k * 2;

    float acc[2][4][4];
    int row0 = 0;

    auto mma_pass = [&](int chunk) {
        const uint32_t wb = b_base0 + chunk * WCH;
        #pragma unroll
        for (int ks = 0; ks < 8; ks++) {
            const uint32_t k2 = ks * 32;               // 16 halves = 32 B
            uint32_t a0[4], a1[4], bA[4], bB[4];
            ldsm4(a0[0], a0[1], a0[2], a0[3], a_base + k2);
            ldsm4(a1[0], a1[1], a1[2], a1[3], a_base + 16 * SB + k2);
            ldsm4(bA[0], bA[1], bA[2], bA[3], wb + k2);
            ldsm4(bB[0], bB[1], bB[2], bB[3], wb + 16 * SB + k2);
            mma16816(acc[0][0], a0, bA + 0);
            mma16816(acc[0][1], a0, bA + 2);
            mma16816(acc[0][2], a0, bB + 0);
            mma16816(acc[0][3], a0, bB + 2);
            mma16816(acc[1][0], a1, bA + 0);
            mma16816(acc[1][1], a1, bA + 2);
            mma16816(acc[1][2], a1, bB + 0);
            mma16816(acc[1][3], a1, bB + 2);
        }
    };

    auto add_bias = [&](const float* __restrict__ bias, bool relu) {
        #pragma unroll
        for (int j = 0; j < 4; j++) {
            int col = wx * 32 + j * 8 + 2 * tig;
            float2 bb = __ldg((const float2*)(bias + col));
            #pragma unroll
            for (int i = 0; i < 2; i++) {
                acc[i][j][0] += bb.x; acc[i][j][1] += bb.y;
                acc[i][j][2] += bb.x; acc[i][j][3] += bb.y;
                if (relu) {
                    acc[i][j][0] = fmaxf(acc[i][j][0], 0.f);
                    acc[i][j][1] = fmaxf(acc[i][j][1], 0.f);
                    acc[i][j][2] = fmaxf(acc[i][j][2], 0.f);
                    acc[i][j][3] = fmaxf(acc[i][j][3], 0.f);
                }
            }
        }
    };

    auto store_act = [&]() {   // write fp16 activations straight into A plane
        #pragma unroll
        for (int i = 0; i < 2; i++) {
            int r0 = wy * 32 + i * 16 + g;
            #pragma unroll
            for (int j = 0; j < 4; j++) {
                int col = wx * 32 + j * 8 + 2 * tig;
                __half2 h0 = __floats2half2_rn(acc[i][j][0], acc[i][j][1]);
                __half2 h1 = __floats2half2_rn(acc[i][j][2], acc[i][j][3]);
                *(uint32_t*)(smem + SA + r0 * SB + col * 2) = *(uint32_t*)&h0;
                *(uint32_t*)(smem + SA + (r0 + 8) * SB + col * 2) = *(uint32_t*)&h1;
            }
        }
    };

    auto zero_acc = [&]() {
        #pragma unroll
        for (int i = 0; i < 2; i++)
            #pragma unroll
            for (int j = 0; j < 4; j++)
                #pragma unroll
                for (int k = 0; k < 4; k++) acc[i][j][k] = 0.f;
    };

    auto stage_a = [&](const float4* __restrict__ src) {
        #pragma unroll
        for (int it = 0; it < 8; it++) {
            int i = tid + it * 512;            // 4096 float4
            int r = i >> 5, c4 = i & 31;
            int rr = row0 + r; if (rr >= nrows) rr = nrows - 1;
            float4 w = src[(size_t)rr * 32 + c4];
            __half2 h0 = __floats2half2_rn(w.x, w.y);
            __half2 h1 = __floats2half2_rn(w.z, w.w);
            uint2 p;
            p.x = *(uint32_t*)&h0;
            p.y = *(uint32_t*)&h1;
            *(uint2*)(smem + SA + r * SB + c4 * 8) = p;
        }
    };

    // =================== persistent tile loop ===================
    for (int tile = blockIdx.x; tile < ntiles; tile += gridDim.x) {
        row0 = tile * 128;
        zero_acc();

        // ---- layer 0: relu([x | msg] @ W0 + b0) ----
        stage_a((const float4*)x);
        __syncthreads();
        mma_pass(0);
        __syncthreads();
        stage_a((const float4*)msgf);
        __syncthreads();
        mma_pass(1);
        __syncthreads();
        add_bias(b0, true);
        store_act();
        zero_acc();
        __syncthreads();

        // ---- hidden layers 1,2 ----
        mma_pass(2);
        __syncthreads();
        add_bias(bh, true);
        store_act();
        zero_acc();
        __syncthreads();
        mma_pass(3);
        __syncthreads();
        add_bias(bh + 128, true);
        store_act();
        zero_acc();
        __syncthreads();

        // ---- output layer + GroupNorm + residual ----
        mma_pass(4);
        __syncthreads();               // A plane dead -> reuse as reduction scratch
        add_bias(bo, false);

        float2* red = (float2*)smem;   // [row][wx] partials, 4 KB
        float mu[2][2], rs[2][2];
        #pragma unroll
        for (int i = 0; i < 2; i++)
            #pragma unroll
            for (int h = 0; h < 2; h++) {
                float s = 0.f, ss = 0.f;
                #pragma unroll
                for (int j = 0; j < 4; j++) {
                    float a = acc[i][j][2 * h], b = acc[i][j][2 * h + 1];
                    s += a + b; ss += a * a + b * b;
                }
                s  += __shfl_xor_sync(0xFFFFFFFFu, s,  1);
                ss += __shfl_xor_sync(0xFFFFFFFFu, ss, 1);
                s  += __shfl_xor_sync(0xFFFFFFFFu, s,  2);
                ss += __shfl_xor_sync(0xFFFFFFFFu, ss, 2);
                if (tig == 0) {
                    int row = wy * 32 + i * 16 + h * 8 + g;
                    red[row * 4 + wx] = make_float2(s, ss);
                }
            }
        __syncthreads();
        #pragma unroll
        for (int i = 0; i < 2; i++)
            #pragma unroll
            for (int h = 0; h < 2; h++) {
                int row = wy * 32 + i * 16 + h * 8 + g;
                float2 t0 = red[row * 4 + 0], t1 = red[row * 4 + 1];
                float2 t2 = red[row * 4 + 2], t3 = red[row * 4 + 3];
                float s  = t0.x + t1.x + t2.x + t3.x;
                float ss = t0.y + t1.y + t2.y + t3.y;
                float m = s * (1.f / 128.f);
                mu[i][h] = m;
                rs[i][h] = rsqrtf(ss * (1.f / 128.f) - m * m + 1e-5f);
            }
        #pragma unroll
        for (int i = 0; i < 2; i++)
            #pragma unroll
            for (int h = 0; h < 2; h++) {
                int row = wy * 32 + i * 16 + h * 8 + g;
                int rg = row0 + row;
                if (rg >= nrows) continue;
                float m = mu[i][h], r = rs[i][h];
                #pragma unroll
                for (int j = 0; j < 4; j++) {
                    int col = wx * 32 + j * 8 + 2 * tig;
                    float2 xg  = __ldg((const float2*)(x + (size_t)rg * 128 + col));
                    float2 gwv = __ldg((const float2*)(gw + col));
                    float2 gbv = __ldg((const float2*)(gb + col));
                    float2 o;
                    o.x = xg.x + (acc[i][j][2 * h]     - m) * r * gwv.x + gbv.x;
                    o.y = xg.y + (acc[i][j][2 * h + 1] - m) * r * gwv.y + gbv.y;
                    *(float2*)(outf + (size_t)rg * 128 + col) = o;
                }
            }
        __syncthreads();               // red region reads done before next stage_a
    }
}

// ---------------------------------------------------------------------------
// launch  (order: prep, zero, dummy, scatter, fused -> scatter at ncu slot 3)
// ---------------------------------------------------------------------------
extern "C" void kernel_launch(void* const* d_in, const int* in_sizes, int n_in,
                              void* d_out, int out_size) {
    const float* x  = (const float*)d_in[0];
    const float* e  = (const float*)d_in[1];
    const void*  ei = d_in[2];
    const float* W0 = (const float*)d_in[3];
    const float* b0 = (const float*)d_in[4];
    const float* Wh = (const float*)d_in[5];
    const float* bh = (const float*)d_in[6];
    const float* Wo = (const float*)d_in[7];
    const float* bo = (const float*)d_in[8];
    const float* gw = (const float*)d_in[9];
    const float* gb = (const float*)d_in[10];
    float* out = (float*)d_out;

    float4* msg;
    __half* w;
    cudaGetSymbolAddress((void**)&msg, g_msg);
    cudaGetSymbolAddress((void**)&w, g_w);

    static int nsm = 0;
    if (nsm == 0) cudaDeviceGetAttribute(&nsm, cudaDevAttrMultiProcessorCount, 0);

    cudaFuncSetAttribute(fused_mlp_kernel, cudaFuncAttributeMaxDynamicSharedMemorySize, SMEM_T);

    prep_kernel<<<(5 * 128 * 128 + 255) / 256, 256>>>(W0, Wh, Wo, ei);
    zero_kernel<<<(N_NODES * 32 + 255) / 256, 256>>>(msg, N_NODES * 32);
    dummy_kernel<<<1, 32>>>();
    scatter_kernel<<<N_EDGES / 8, 256>>>((const float4*)e, ei, msg);

    const int ntiles = (N_NODES + 127) / 128;    // 782
    fused_mlp_kernel<<<nsm, 512, SMEM_T>>>(
        x, (const float*)msg, w, b0, bh, bo, gw, gb, out, N_NODES, ntiles);
}

// round 16
// speedup vs baseline: 1.0915x; 1.0915x over previous
#include <cuda_runtime.h>
#include <cuda_fp16.h>
#include <cstdint>

#define N_NODES 100000
#define N_EDGES 1600000

// ---------------------------------------------------------------------------
// Device scratch
// ---------------------------------------------------------------------------
__device__ float4 g_msg[(size_t)N_NODES * 32];   // 51.2 MB
__device__ __half g_w[5 * 128 * 128];            // W^T fp16 planes [chunk][n][k]
__device__ int    g_mode;

// ---------------------------------------------------------------------------
// weight prep (transpose to [n][k], fp16) + edge_index dtype detection
// chunk 0,1 = W0 (k 0-127 / 128-255); 2,3 = Wh[0],Wh[1]; 4 = Wo
// ---------------------------------------------------------------------------
__global__ void prep_kernel(const float* __restrict__ W0,
                            const float* __restrict__ Wh,
                            const float* __restrict__ Wo,
                            const void* eiv) {
    if (blockIdx.x == 0 && threadIdx.x == 0) {
        const long long* e64 = (const long long*)eiv;
        const int*       e32 = (const int*)eiv;
        const float*     ef  = (const float*)eiv;
        bool ok64 = true, ok32 = true, okf = true;
        for (int i = 0; i < 32; i++) {
            long long v = e64[i];
            if (v < 0 || v >= N_NODES) ok64 = false;
            int w = e32[i];
            if (w < 0 || w >= N_NODES) ok32 = false;
            float f = ef[i];
            if (!(f >= 0.f && f < (float)N_NODES)) okf = false;
        }
        g_mode = ok64 ? 1 : (ok32 ? 0 : (okf ? 2 : 0));
    }
    int i = blockIdx.x * 256 + threadIdx.x;
    if (i >= 5 * 128 * 128) return;
    int chunk = i >> 14;
    int r = i & 16383;
    int n = r >> 7, k = r & 127;
    float v;
    if (chunk < 2)      v = W0[(chunk * 128 + k) * 128 + n];
    else if (chunk < 4) v = Wh[(chunk - 2) * 16384 + k * 128 + n];
    else                v = Wo[k * 128 + n];
    g_w[i] = __float2half_rn(v);
}

__global__ void zero_kernel(float4* __restrict__ p, int n4) {
    int i = blockIdx.x * blockDim.x + threadIdx.x;
    if (i < n4) p[i] = make_float4(0.f, 0.f, 0.f, 0.f);
}

// no-op: keeps scatter at ncu's captured launch slot (index 3)
__global__ void dummy_kernel() {}

// ---------------------------------------------------------------------------
// scatter-sum: one warp per edge, lane handles 16 B of the 512 B edge row,
// vector RED into the L2-resident msg buffer.
// e and the index row are loaded with an evict-first L2 policy (createpolicy
// + ld.global.nc.L2::cache_hint) — single-touch streaming data must not evict
// the dirty msg accumulator lines (R14 ncu showed ~460 MB parasitic traffic).
// ---------------------------------------------------------------------------
__global__ void scatter_kernel(const float4* __restrict__ e4,
                               const void* __restrict__ eiv,
                               float4* __restrict__ msg) {
    __shared__ int mode;
    if (threadIdx.x == 0) mode = g_mode;
    __syncthreads();
    int warp = (blockIdx.x * blockDim.x + threadIdx.x) >> 5;
    int lane = threadIdx.x & 31;
    if (warp >= N_EDGES) return;

    unsigned long long pol;
    asm("createpolicy.fractional.L2::evict_first.b64 %0, 1.0;" : "=l"(pol));

    int d;
    if (mode == 1) {
        long long t;
        asm("ld.global.nc.L2::cache_hint.s64 %0, [%1], %2;"
            : "=l"(t) : "l"((const long long*)eiv + N_EDGES + warp), "l"(pol));
        d = (int)t;
    } else if (mode == 0) {
        asm("ld.global.nc.L2::cache_hint.s32 %0, [%1], %2;"
            : "=r"(d) : "l"((const int*)eiv + N_EDGES + warp), "l"(pol));
    } else {
        float t;
        asm("ld.global.nc.L2::cache_hint.f32 %0, [%1], %2;"
            : "=f"(t) : "l"((const float*)eiv + N_EDGES + warp), "l"(pol));
        d = (int)t;
    }
    d = min(max(d, 0), N_NODES - 1);
    float4 v;
    asm("ld.global.nc.L2::cache_hint.v4.f32 {%0,%1,%2,%3}, [%4], %5;"
        : "=f"(v.x), "=f"(v.y), "=f"(v.z), "=f"(v.w)
        : "l"(e4 + (size_t)warp * 32 + lane), "l"(pol));
    float4* p = &msg[(size_t)d * 32 + lane];
    asm volatile("red.global.add.v4.f32 [%0], {%1,%2,%3,%4};"
                 :: "l"(p), "f"(v.x), "f"(v.y), "f"(v.z), "f"(v.w) : "memory");
}

// ---------------------------------------------------------------------------
// Fused 4-layer MLP (R13 configuration — best measured).
// 512 threads, one 128-row tile per CTA (grid 782), 16 warps in 4x4 grid.
// Explicit mma.sync.m16n8k16 + ldmatrix; bias/ReLU/fp16-convert in registers;
// A plane rewritten in place between layers; all 5 W chunks smem-resident.
// smem: A fp16 plane 128x272B | W chunks 5x(128x272B) = 208,960 B.
// ---------------------------------------------------------------------------
#define SSTR 136
#define SB   272                         // bytes per plane row
#define SA   0
#define SWB  (128 * SB)                  // 34816: W region base
#define WCH  (128 * SB)                  // per-chunk size
#define SMEM_T (SWB + 5 * WCH + 64)      // 208960

__device__ __forceinline__ void ldsm4(uint32_t& r0, uint32_t& r1,
                                      uint32_t& r2, uint32_t& r3, uint32_t a) {
    asm volatile("ldmatrix.sync.aligned.m8n8.x4.shared.b16 {%0,%1,%2,%3}, [%4];"
                 : "=r"(r0), "=r"(r1), "=r"(r2), "=r"(r3) : "r"(a));
}

__device__ __forceinline__ void mma16816(float* d, const uint32_t* a, const uint32_t* b) {
    asm volatile("mma.sync.aligned.m16n8k16.row.col.f32.f16.f16.f32 "
                 "{%0,%1,%2,%3}, {%4,%5,%6,%7}, {%8,%9}, {%0,%1,%2,%3};"
                 : "+f"(d[0]), "+f"(d[1]), "+f"(d[2]), "+f"(d[3])
                 : "r"(a[0]), "r"(a[1]), "r"(a[2]), "r"(a[3]), "r"(b[0]), "r"(b[1]));
}

__global__ void __launch_bounds__(512, 1)
fused_mlp_kernel(const float* __restrict__ x, const float* __restrict__ msgf,
                 const __half* __restrict__ W_g,
                 const float* __restrict__ b0, const float* __restrict__ bh,
                 const float* __restrict__ bo,
                 const float* __restrict__ gw, const float* __restrict__ gb,
                 float* __restrict__ outf, int nrows) {
    extern __shared__ char smem[];
    const int tid  = threadIdx.x;
    const int wid  = tid >> 5, lane = tid & 31;
    const int wy   = wid >> 2, wx = wid & 3;      // 4x4 warp grid, 32x32 tiles
    const int g    = lane >> 2, tig = lane & 3;   // mma quad coords
    const int row0 = blockIdx.x * 128;

    // ---- stage ALL weight chunks (10240 uint4) ----
    {
        const uint4* w4 = (const uint4*)W_g;
        #pragma unroll
        for (int it = 0; it < 20; it++) {
            int i = tid + it * 512;
            int chunk = i >> 11;
            int n = (i & 2047) >> 4, c16 = i & 15;
            *(uint4*)(smem + SWB + chunk * WCH + n * SB + c16 * 16) = w4[i];
        }
    }

    // ldmatrix lane-address components
    const uint32_t sbase = (uint32_t)__cvta_generic_to_shared(smem);
    const uint32_t a_row = wy * 32 + (lane & 15);           // + i*16
    const uint32_t a_k   = (lane >> 4) << 3;
    const uint32_t b_row = wx * 32 + (lane & 7) + ((lane >> 4) << 3);  // + p*16
    const uint32_t b_k   = ((lane >> 3) & 1) << 3;
    const uint32_t a_base = sbase + SA + a_row * SB + a_k * 2;
    const uint32_t b_base0 = sbase + SWB + b_row * SB + b_k * 2;

    float acc[2][4][4];
    #pragma unroll
    for (int i = 0; i < 2; i++)
        #pragma unroll
        for (int j = 0; j < 4; j++)
            #pragma unroll
            for (int k = 0; k < 4; k++) acc[i][j][k] = 0.f;

    auto mma_pass = [&](int chunk) {
        const uint32_t wb = b_base0 + chunk * WCH;
        #pragma unroll
        for (int ks = 0; ks < 8; ks++) {
            const uint32_t k2 = ks * 32;               // 16 halves = 32 B
            uint32_t a0[4], a1[4], bA[4], bB[4];
            ldsm4(a0[0], a0[1], a0[2], a0[3], a_base + k2);
            ldsm4(a1[0], a1[1], a1[2], a1[3], a_base + 16 * SB + k2);
            ldsm4(bA[0], bA[1], bA[2], bA[3], wb + k2);
            ldsm4(bB[0], bB[1], bB[2], bB[3], wb + 16 * SB + k2);
            mma16816(acc[0][0], a0, bA + 0);
            mma16816(acc[0][1], a0, bA + 2);
            mma16816(acc[0][2], a0, bB + 0);
            mma16816(acc[0][3], a0, bB + 2);
            mma16816(acc[1][0], a1, bA + 0);
            mma16816(acc[1][1], a1, bA + 2);
            mma16816(acc[1][2], a1, bB + 0);
            mma16816(acc[1][3], a1, bB + 2);
        }
    };

    auto add_bias = [&](const float* __restrict__ bias, bool relu) {
        #pragma unroll
        for (int j = 0; j < 4; j++) {
            int col = wx * 32 + j * 8 + 2 * tig;
            float2 bb = __ldg((const float2*)(bias + col));
            #pragma unroll
            for (int i = 0; i < 2; i++) {
                acc[i][j][0] += bb.x; acc[i][j][1] += bb.y;
                acc[i][j][2] += bb.x; acc[i][j][3] += bb.y;
                if (relu) {
                    acc[i][j][0] = fmaxf(acc[i][j][0], 0.f);
                    acc[i][j][1] = fmaxf(acc[i][j][1], 0.f);
                    acc[i][j][2] = fmaxf(acc[i][j][2], 0.f);
                    acc[i][j][3] = fmaxf(acc[i][j][3], 0.f);
                }
            }
        }
    };

    auto store_act = [&]() {   // write fp16 activations straight into A plane
        #pragma unroll
        for (int i = 0; i < 2; i++) {
            int r0 = wy * 32 + i * 16 + g;
            #pragma unroll
            for (int j = 0; j < 4; j++) {
                int col = wx * 32 + j * 8 + 2 * tig;
                __half2 h0 = __floats2half2_rn(acc[i][j][0], acc[i][j][1]);
                __half2 h1 = __floats2half2_rn(acc[i][j][2], acc[i][j][3]);
                *(uint32_t*)(smem + SA + r0 * SB + col * 2) = *(uint32_t*)&h0;
                *(uint32_t*)(smem + SA + (r0 + 8) * SB + col * 2) = *(uint32_t*)&h1;
            }
        }
    };

    auto zero_acc = [&]() {
        #pragma unroll
        for (int i = 0; i < 2; i++)
            #pragma unroll
            for (int j = 0; j < 4; j++)
                #pragma unroll
                for (int k = 0; k < 4; k++) acc[i][j][k] = 0.f;
    };

    auto stage_a = [&](const float4* __restrict__ src) {
        #pragma unroll
        for (int it = 0; it < 8; it++) {
            int i = tid + it * 512;            // 4096 float4
            int r = i >> 5, c4 = i & 31;
            int rr = row0 + r; if (rr >= nrows) rr = nrows - 1;
            float4 w = src[(size_t)rr * 32 + c4];
            __half2 h0 = __floats2half2_rn(w.x, w.y);
            __half2 h1 = __floats2half2_rn(w.z, w.w);
            uint2 p;
            p.x = *(uint32_t*)&h0;
            p.y = *(uint32_t*)&h1;
            *(uint2*)(smem + SA + r * SB + c4 * 8) = p;
        }
    };

    // ================= layer 0: relu([x | msg] @ W0 + b0) =================
    stage_a((const float4*)x);
    __syncthreads();                 // also covers W staging
    mma_pass(0);
    __syncthreads();
    stage_a((const float4*)msgf);
    __syncthreads();
    mma_pass(1);
    __syncthreads();
    add_bias(b0, true);
    store_act();
    zero_acc();
    __syncthreads();

    // ================= hidden layers 1,2 =================
    mma_pass(2);
    __syncthreads();
    add_bias(bh, true);
    store_act();
    zero_acc();
    __syncthreads();
    mma_pass(3);
    __syncthreads();
    add_bias(bh + 128, true);
    store_act();
    zero_acc();
    __syncthreads();

    // ================= output layer + GroupNorm + residual =================
    mma_pass(4);
    __syncthreads();                 // A plane dead -> reuse as reduction scratch
    add_bias(bo, false);

    float2* red = (float2*)smem;     // [row][wx] partials, 4 KB
    float mu[2][2], rs[2][2];
    #pragma unroll
    for (int i = 0; i < 2; i++)
        #pragma unroll
        for (int h = 0; h < 2; h++) {
            float s = 0.f, ss = 0.f;
            #pragma unroll
            for (int j = 0; j < 4; j++) {
                float a = acc[i][j][2 * h], b = acc[i][j][2 * h + 1];
                s += a + b; ss += a * a + b * b;
            }
            s  += __shfl_xor_sync(0xFFFFFFFFu, s,  1);
            ss += __shfl_xor_sync(0xFFFFFFFFu, ss, 1);
            s  += __shfl_xor_sync(0xFFFFFFFFu, s,  2);
            ss += __shfl_xor_sync(0xFFFFFFFFu, ss, 2);
            if (tig == 0) {
                int row = wy * 32 + i * 16 + h * 8 + g;
                red[row * 4 + wx] = make_float2(s, ss);
            }
        }
    __syncthreads();
    #pragma unroll
    for (int i = 0; i < 2; i++)
        #pragma unroll
        for (int h = 0; h < 2; h++) {
            int row = wy * 32 + i * 16 + h * 8 + g;
            float2 t0 = red[row * 4 + 0], t1 = red[row * 4 + 1];
            float2 t2 = red[row * 4 + 2], t3 = red[row * 4 + 3];
            float s  = t0.x + t1.x + t2.x + t3.x;
            float ss = t0.y + t1.y + t2.y + t3.y;
            float m = s * (1.f / 128.f);
            mu[i][h] = m;
            rs[i][h] = rsqrtf(ss * (1.f / 128.f) - m * m + 1e-5f);
        }
    #pragma unroll
    for (int i = 0; i < 2; i++)
        #pragma unroll
        for (int h = 0; h < 2; h++) {
            int row = wy * 32 + i * 16 + h * 8 + g;
            int rg = row0 + row;
            if (rg >= nrows) continue;
            float m = mu[i][h], r = rs[i][h];
            #pragma unroll
            for (int j = 0; j < 4; j++) {
                int col = wx * 32 + j * 8 + 2 * tig;
                float2 xg  = __ldg((const float2*)(x + (size_t)rg * 128 + col));
                float2 gwv = __ldg((const float2*)(gw + col));
                float2 gbv = __ldg((const float2*)(gb + col));
                float2 o;
                o.x = xg.x + (acc[i][j][2 * h]     - m) * r * gwv.x + gbv.x;
                o.y = xg.y + (acc[i][j][2 * h + 1] - m) * r * gwv.y + gbv.y;
                *(float2*)(outf + (size_t)rg * 128 + col) = o;
            }
        }
}

// ---------------------------------------------------------------------------
// launch  (order: prep, zero, dummy, scatter, fused -> scatter at ncu slot 3)
// ---------------------------------------------------------------------------
extern "C" void kernel_launch(void* const* d_in, const int* in_sizes, int n_in,
                              void* d_out, int out_size) {
    const float* x  = (const float*)d_in[0];
    const float* e  = (const float*)d_in[1];
    const void*  ei = d_in[2];
    const float* W0 = (const float*)d_in[3];
    const float* b0 = (const float*)d_in[4];
    const float* Wh = (const float*)d_in[5];
    const float* bh = (const float*)d_in[6];
    const float* Wo = (const float*)d_in[7];
    const float* bo = (const float*)d_in[8];
    const float* gw = (const float*)d_in[9];
    const float* gb = (const float*)d_in[10];
    float* out = (float*)d_out;

    float4* msg;
    __half* w;
    cudaGetSymbolAddress((void**)&msg, g_msg);
    cudaGetSymbolAddress((void**)&w, g_w);

    cudaFuncSetAttribute(fused_mlp_kernel, cudaFuncAttributeMaxDynamicSharedMemorySize, SMEM_T);

    prep_kernel<<<(5 * 128 * 128 + 255) / 256, 256>>>(W0, Wh, Wo, ei);
    zero_kernel<<<(N_NODES * 32 + 255) / 256, 256>>>(msg, N_NODES * 32);
    dummy_kernel<<<1, 32>>>();
    scatter_kernel<<<N_EDGES / 8, 256>>>((const float4*)e, ei, msg);

    const int gblocks = (N_NODES + 127) / 128;   // 782
    fused_mlp_kernel<<<gblocks, 512, SMEM_T>>>(
        x, (const float*)msg, w, b0, bh, bo, gw, gb, out, N_NODES);
}

// round 17
// speedup vs baseline: 1.1612x; 1.0638x over previous
#include <cuda_runtime.h>
#include <cuda_fp16.h>
#include <cstdint>

#define N_NODES 100000
#define N_EDGES 1600000

// ---------------------------------------------------------------------------
// Device scratch
// ---------------------------------------------------------------------------
__device__ float4 g_msg[(size_t)N_NODES * 32];   // 51.2 MB
__device__ __half g_w[5 * 128 * 128];            // W^T fp16 planes [chunk][n][k]
__device__ int    g_mode;

// ---------------------------------------------------------------------------
// weight prep (transpose to [n][k], fp16) + edge_index dtype detection
// chunk 0,1 = W0 (k 0-127 / 128-255); 2,3 = Wh[0],Wh[1]; 4 = Wo
// ---------------------------------------------------------------------------
__global__ void prep_kernel(const float* __restrict__ W0,
                            const float* __restrict__ Wh,
                            const float* __restrict__ Wo,
                            const void* eiv) {
    if (blockIdx.x == 0 && threadIdx.x == 0) {
        const long long* e64 = (const long long*)eiv;
        const int*       e32 = (const int*)eiv;
        const float*     ef  = (const float*)eiv;
        bool ok64 = true, ok32 = true, okf = true;
        for (int i = 0; i < 32; i++) {
            long long v = e64[i];
            if (v < 0 || v >= N_NODES) ok64 = false;
            int w = e32[i];
            if (w < 0 || w >= N_NODES) ok32 = false;
            float f = ef[i];
            if (!(f >= 0.f && f < (float)N_NODES)) okf = false;
        }
        g_mode = ok64 ? 1 : (ok32 ? 0 : (okf ? 2 : 0));
    }
    int i = blockIdx.x * 256 + threadIdx.x;
    if (i >= 5 * 128 * 128) return;
    int chunk = i >> 14;
    int r = i & 16383;
    int n = r >> 7, k = r & 127;
    float v;
    if (chunk < 2)      v = W0[(chunk * 128 + k) * 128 + n];
    else if (chunk < 4) v = Wh[(chunk - 2) * 16384 + k * 128 + n];
    else                v = Wo[k * 128 + n];
    g_w[i] = __float2half_rn(v);
}

__global__ void zero_kernel(float4* __restrict__ p, int n4) {
    int i = blockIdx.x * blockDim.x + threadIdx.x;
    if (i < n4) p[i] = make_float4(0.f, 0.f, 0.f, 0.f);
}

// no-op: keeps scatter at ncu's captured launch slot (index 3)
__global__ void dummy_kernel() {}

// ---------------------------------------------------------------------------
// scatter-sum, 4 edges per warp, batched: one vector index load + four
// LDG.128 e-row loads issued BEFORE any RED (MLP_eff = 4). Lane covers 16 B
// of each 512 B edge row. Streaming loads use an evict-first L2 policy so the
// single-touch edge stream does not evict the dirty msg accumulator (R16 ncu:
// traffic 1.29 -> 0.93 GB from this policy). N_EDGES % 4 == 0: no guards.
// ---------------------------------------------------------------------------
__global__ void scatter_kernel(const float4* __restrict__ e4,
                               const void* __restrict__ eiv,
                               float4* __restrict__ msg) {
    __shared__ int mode;
    if (threadIdx.x == 0) mode = g_mode;
    __syncthreads();
    int warp = (blockIdx.x * blockDim.x + threadIdx.x) >> 5;
    int lane = threadIdx.x & 31;
    int e0 = warp * 4;
    if (e0 >= N_EDGES) return;

    unsigned long long pol;
    asm("createpolicy.fractional.L2::evict_first.b64 %0, 1.0;" : "=l"(pol));

    // ---- phase 1: all loads ----
    int d[4];
    if (mode == 1) {
        long long t0, t1, t2, t3;
        asm("ld.global.nc.L2::cache_hint.v2.s64 {%0,%1}, [%2], %3;"
            : "=l"(t0), "=l"(t1)
            : "l"((const long long*)eiv + N_EDGES + e0), "l"(pol));
        asm("ld.global.nc.L2::cache_hint.v2.s64 {%0,%1}, [%2], %3;"
            : "=l"(t2), "=l"(t3)
            : "l"((const long long*)eiv + N_EDGES + e0 + 2), "l"(pol));
        d[0] = (int)t0; d[1] = (int)t1; d[2] = (int)t2; d[3] = (int)t3;
    } else if (mode == 0) {
        asm("ld.global.nc.L2::cache_hint.v4.s32 {%0,%1,%2,%3}, [%4], %5;"
            : "=r"(d[0]), "=r"(d[1]), "=r"(d[2]), "=r"(d[3])
            : "l"((const int*)eiv + N_EDGES + e0), "l"(pol));
    } else {
        float f0, f1, f2, f3;
        asm("ld.global.nc.L2::cache_hint.v4.f32 {%0,%1,%2,%3}, [%4], %5;"
            : "=f"(f0), "=f"(f1), "=f"(f2), "=f"(f3)
            : "l"((const float*)eiv + N_EDGES + e0), "l"(pol));
        d[0] = (int)f0; d[1] = (int)f1; d[2] = (int)f2; d[3] = (int)f3;
    }
    float4 v[4];
    #pragma unroll
    for (int k = 0; k < 4; k++) {
        asm("ld.global.nc.L2::cache_hint.v4.f32 {%0,%1,%2,%3}, [%4], %5;"
            : "=f"(v[k].x), "=f"(v[k].y), "=f"(v[k].z), "=f"(v[k].w)
            : "l"(e4 + (size_t)(e0 + k) * 32 + lane), "l"(pol));
    }

    // ---- phase 2: all REDs ----
    #pragma unroll
    for (int k = 0; k < 4; k++) {
        int dd = min(max(d[k], 0), N_NODES - 1);
        float4* p = &msg[(size_t)dd * 32 + lane];
        asm volatile("red.global.add.v4.f32 [%0], {%1,%2,%3,%4};"
                     :: "l"(p), "f"(v[k].x), "f"(v[k].y), "f"(v[k].z), "f"(v[k].w)
                     : "memory");
    }
}

// ---------------------------------------------------------------------------
// Fused 4-layer MLP (R13 configuration — best measured, 97.5 us).
// 512 threads, one 128-row tile per CTA (grid 782), 16 warps in 4x4 grid.
// Explicit mma.sync.m16n8k16 + ldmatrix; bias/ReLU/fp16-convert in registers;
// A plane rewritten in place between layers; all 5 W chunks smem-resident.
// smem: A fp16 plane 128x272B | W chunks 5x(128x272B) = 208,960 B.
// ---------------------------------------------------------------------------
#define SSTR 136
#define SB   272                         // bytes per plane row
#define SA   0
#define SWB  (128 * SB)                  // 34816: W region base
#define WCH  (128 * SB)                  // per-chunk size
#define SMEM_T (SWB + 5 * WCH + 64)      // 208960

__device__ __forceinline__ void ldsm4(uint32_t& r0, uint32_t& r1,
                                      uint32_t& r2, uint32_t& r3, uint32_t a) {
    asm volatile("ldmatrix.sync.aligned.m8n8.x4.shared.b16 {%0,%1,%2,%3}, [%4];"
                 : "=r"(r0), "=r"(r1), "=r"(r2), "=r"(r3) : "r"(a));
}

__device__ __forceinline__ void mma16816(float* d, const uint32_t* a, const uint32_t* b) {
    asm volatile("mma.sync.aligned.m16n8k16.row.col.f32.f16.f16.f32 "
                 "{%0,%1,%2,%3}, {%4,%5,%6,%7}, {%8,%9}, {%0,%1,%2,%3};"
                 : "+f"(d[0]), "+f"(d[1]), "+f"(d[2]), "+f"(d[3])
                 : "r"(a[0]), "r"(a[1]), "r"(a[2]), "r"(a[3]), "r"(b[0]), "r"(b[1]));
}

__global__ void __launch_bounds__(512, 1)
fused_mlp_kernel(const float* __restrict__ x, const float* __restrict__ msgf,
                 const __half* __restrict__ W_g,
                 const float* __restrict__ b0, const float* __restrict__ bh,
                 const float* __restrict__ bo,
                 const float* __restrict__ gw, const float* __restrict__ gb,
                 float* __restrict__ outf, int nrows) {
    extern __shared__ char smem[];
    const int tid  = threadIdx.x;
    const int wid  = tid >> 5, lane = tid & 31;
    const int wy   = wid >> 2, wx = wid & 3;      // 4x4 warp grid, 32x32 tiles
    const int g    = lane >> 2, tig = lane & 3;   // mma quad coords
    const int row0 = blockIdx.x * 128;

    // ---- stage ALL weight chunks (10240 uint4) ----
    {
        const uint4* w4 = (const uint4*)W_g;
        #pragma unroll
        for (int it = 0; it < 20; it++) {
            int i = tid + it * 512;
            int chunk = i >> 11;
            int n = (i & 2047) >> 4, c16 = i & 15;
            *(uint4*)(smem + SWB + chunk * WCH + n * SB + c16 * 16) = w4[i];
        }
    }

    // ldmatrix lane-address components
    const uint32_t sbase = (uint32_t)__cvta_generic_to_shared(smem);
    const uint32_t a_row = wy * 32 + (lane & 15);           // + i*16
    const uint32_t a_k   = (lane >> 4) << 3;
    const uint32_t b_row = wx * 32 + (lane & 7) + ((lane >> 4) << 3);  // + p*16
    const uint32_t b_k   = ((lane >> 3) & 1) << 3;
    const uint32_t a_base = sbase + SA + a_row * SB + a_k * 2;
    const uint32_t b_base0 = sbase + SWB + b_row * SB + b_k * 2;

    float acc[2][4][4];
    #pragma unroll
    for (int i = 0; i < 2; i++)
        #pragma unroll
        for (int j = 0; j < 4; j++)
            #pragma unroll
            for (int k = 0; k < 4; k++) acc[i][j][k] = 0.f;

    auto mma_pass = [&](int chunk) {
        const uint32_t wb = b_base0 + chunk * WCH;
        #pragma unroll
        for (int ks = 0; ks < 8; ks++) {
            const uint32_t k2 = ks * 32;               // 16 halves = 32 B
            uint32_t a0[4], a1[4], bA[4], bB[4];
            ldsm4(a0[0], a0[1], a0[2], a0[3], a_base + k2);
            ldsm4(a1[0], a1[1], a1[2], a1[3], a_base + 16 * SB + k2);
            ldsm4(bA[0], bA[1], bA[2], bA[3], wb + k2);
            ldsm4(bB[0], bB[1], bB[2], bB[3], wb + 16 * SB + k2);
            mma16816(acc[0][0], a0, bA + 0);
            mma16816(acc[0][1], a0, bA + 2);
            mma16816(acc[0][2], a0, bB + 0);
            mma16816(acc[0][3], a0, bB + 2);
            mma16816(acc[1][0], a1, bA + 0);
            mma16816(acc[1][1], a1, bA + 2);
            mma16816(acc[1][2], a1, bB + 0);
            mma16816(acc[1][3], a1, bB + 2);
        }
    };

    auto add_bias = [&](const float* __restrict__ bias, bool relu) {
        #pragma unroll
        for (int j = 0; j < 4; j++) {
            int col = wx * 32 + j * 8 + 2 * tig;
            float2 bb = __ldg((const float2*)(bias + col));
            #pragma unroll
            for (int i = 0; i < 2; i++) {
                acc[i][j][0] += bb.x; acc[i][j][1] += bb.y;
                acc[i][j][2] += bb.x; acc[i][j][3] += bb.y;
                if (relu) {
                    acc[i][j][0] = fmaxf(acc[i][j][0], 0.f);
                    acc[i][j][1] = fmaxf(acc[i][j][1], 0.f);
                    acc[i][j][2] = fmaxf(acc[i][j][2], 0.f);
                    acc[i][j][3] = fmaxf(acc[i][j][3], 0.f);
                }
            }
        }
    };

    auto store_act = [&]() {   // write fp16 activations straight into A plane
        #pragma unroll
        for (int i = 0; i < 2; i++) {
            int r0 = wy * 32 + i * 16 + g;
            #pragma unroll
            for (int j = 0; j < 4; j++) {
                int col = wx * 32 + j * 8 + 2 * tig;
                __half2 h0 = __floats2half2_rn(acc[i][j][0], acc[i][j][1]);
                __half2 h1 = __floats2half2_rn(acc[i][j][2], acc[i][j][3]);
                *(uint32_t*)(smem + SA + r0 * SB + col * 2) = *(uint32_t*)&h0;
                *(uint32_t*)(smem + SA + (r0 + 8) * SB + col * 2) = *(uint32_t*)&h1;
            }
        }
    };

    auto zero_acc = [&]() {
        #pragma unroll
        for (int i = 0; i < 2; i++)
            #pragma unroll
            for (int j = 0; j < 4; j++)
                #pragma unroll
                for (int k = 0; k < 4; k++) acc[i][j][k] = 0.f;
    };

    auto stage_a = [&](const float4* __restrict__ src) {
        #pragma unroll
        for (int it = 0; it < 8; it++) {
            int i = tid + it * 512;            // 4096 float4
            int r = i >> 5, c4 = i & 31;
            int rr = row0 + r; if (rr >= nrows) rr = nrows - 1;
            float4 w = src[(size_t)rr * 32 + c4];
            __half2 h0 = __floats2half2_rn(w.x, w.y);
            __half2 h1 = __floats2half2_rn(w.z, w.w);
            uint2 p;
            p.x = *(uint32_t*)&h0;
            p.y = *(uint32_t*)&h1;
            *(uint2*)(smem + SA + r * SB + c4 * 8) = p;
        }
    };

    // ================= layer 0: relu([x | msg] @ W0 + b0) =================
    stage_a((const float4*)x);
    __syncthreads();                 // also covers W staging
    mma_pass(0);
    __syncthreads();
    stage_a((const float4*)msgf);
    __syncthreads();
    mma_pass(1);
    __syncthreads();
    add_bias(b0, true);
    store_act();
    zero_acc();
    __syncthreads();

    // ================= hidden layers 1,2 =================
    mma_pass(2);
    __syncthreads();
    add_bias(bh, true);
    store_act();
    zero_acc();
    __syncthreads();
    mma_pass(3);
    __syncthreads();
    add_bias(bh + 128, true);
    store_act();
    zero_acc();
    __syncthreads();

    // ================= output layer + GroupNorm + residual =================
    mma_pass(4);
    __syncthreads();                 // A plane dead -> reuse as reduction scratch
    add_bias(bo, false);

    float2* red = (float2*)smem;     // [row][wx] partials, 4 KB
    float mu[2][2], rs[2][2];
    #pragma unroll
    for (int i = 0; i < 2; i++)
        #pragma unroll
        for (int h = 0; h < 2; h++) {
            float s = 0.f, ss = 0.f;
            #pragma unroll
            for (int j = 0; j < 4; j++) {
                float a = acc[i][j][2 * h], b = acc[i][j][2 * h + 1];
                s += a + b; ss += a * a + b * b;
            }
            s  += __shfl_xor_sync(0xFFFFFFFFu, s,  1);
            ss += __shfl_xor_sync(0xFFFFFFFFu, ss, 1);
            s  += __shfl_xor_sync(0xFFFFFFFFu, s,  2);
            ss += __shfl_xor_sync(0xFFFFFFFFu, ss, 2);
            if (tig == 0) {
                int row = wy * 32 + i * 16 + h * 8 + g;
                red[row * 4 + wx] = make_float2(s, ss);
            }
        }
    __syncthreads();
    #pragma unroll
    for (int i = 0; i < 2; i++)
        #pragma unroll
        for (int h = 0; h < 2; h++) {
            int row = wy * 32 + i * 16 + h * 8 + g;
            float2 t0 = red[row * 4 + 0], t1 = red[row * 4 + 1];
            float2 t2 = red[row * 4 + 2], t3 = red[row * 4 + 3];
            float s  = t0.x + t1.x + t2.x + t3.x;
            float ss = t0.y + t1.y + t2.y + t3.y;
            float m = s * (1.f / 128.f);
            mu[i][h] = m;
            rs[i][h] = rsqrtf(ss * (1.f / 128.f) - m * m + 1e-5f);
        }
    #pragma unroll
    for (int i = 0; i < 2; i++)
        #pragma unroll
        for (int h = 0; h < 2; h++) {
            int row = wy * 32 + i * 16 + h * 8 + g;
            int rg = row0 + row;
            if (rg >= nrows) continue;
            float m = mu[i][h], r = rs[i][h];
            #pragma unroll
            for (int j = 0; j < 4; j++) {
                int col = wx * 32 + j * 8 + 2 * tig;
                float2 xg  = __ldg((const float2*)(x + (size_t)rg * 128 + col));
                float2 gwv = __ldg((const float2*)(gw + col));
                float2 gbv = __ldg((const float2*)(gb + col));
                float2 o;
                o.x = xg.x + (acc[i][j][2 * h]     - m) * r * gwv.x + gbv.x;
                o.y = xg.y + (acc[i][j][2 * h + 1] - m) * r * gwv.y + gbv.y;
                *(float2*)(outf + (size_t)rg * 128 + col) = o;
            }
        }
}

// ---------------------------------------------------------------------------
// launch  (order: prep, zero, dummy, scatter, fused -> scatter at ncu slot 3)
// ---------------------------------------------------------------------------
extern "C" void kernel_launch(void* const* d_in, const int* in_sizes, int n_in,
                              void* d_out, int out_size) {
    const float* x  = (const float*)d_in[0];
    const float* e  = (const float*)d_in[1];
    const void*  ei = d_in[2];
    const float* W0 = (const float*)d_in[3];
    const float* b0 = (const float*)d_in[4];
    const float* Wh = (const float*)d_in[5];
    const float* bh = (const float*)d_in[6];
    const float* Wo = (const float*)d_in[7];
    const float* bo = (const float*)d_in[8];
    const float* gw = (const float*)d_in[9];
    const float* gb = (const float*)d_in[10];
    float* out = (float*)d_out;

    float4* msg;
    __half* w;
    cudaGetSymbolAddress((void**)&msg, g_msg);
    cudaGetSymbolAddress((void**)&w, g_w);

    cudaFuncSetAttribute(fused_mlp_kernel, cudaFuncAttributeMaxDynamicSharedMemorySize, SMEM_T);

    prep_kernel<<<(5 * 128 * 128 + 255) / 256, 256>>>(W0, Wh, Wo, ei);
    zero_kernel<<<(N_NODES * 32 + 255) / 256, 256>>>(msg, N_NODES * 32);
    dummy_kernel<<<1, 32>>>();
    // 4 edges per warp: 400000 warps -> 50000 blocks of 256 threads
    scatter_kernel<<<(N_EDGES / 4) / 8, 256>>>((const float4*)e, ei, msg);

    const int gblocks = (N_NODES + 127) / 128;   // 782
    fused_mlp_kernel<<<gblocks, 512, SMEM_T>>>(
        x, (const float*)msg, w, b0, bh, bo, gw, gb, out, N_NODES);
}